// round 6
// baseline (speedup 1.0000x reference)
#include <cuda_runtime.h>
#include <math.h>

constexpr int cT = 1024, cS = 1024, cB = 8, cE = 768, cH = 12, cD = 64;

// ---------------- scratch (device globals) ----------------------------------
__device__ float g_q   [cB * cH * cT * cD];            // [B,H,T,D] (pre-scaled)
__device__ float g_k   [cB * cH * cS * cD];            // [B,H,S,D]
__device__ float g_v   [cB * cH * cS * cD];            // [B,H,S,D]
__device__ float g_L   [(size_t)cB * cH * cT * cS];    // [B,H,T,S]: e = exp(logit)
__device__ float g_z   [cB * cH * cT];                 // row sums of e
__device__ float g_attn[cT * cB * cE];                 // [T,B,E]

// ---------------- packed f32x2 helpers (FFMA2 path) --------------------------
using u64 = unsigned long long;
__device__ __forceinline__ u64 pk(float x, float y) {
    u64 r; asm("mov.b64 %0, {%1, %2};" : "=l"(r) : "f"(x), "f"(y)); return r;
}
__device__ __forceinline__ u64 pk1(float x) {
    u64 r; asm("mov.b64 %0, {%1, %1};" : "=l"(r) : "f"(x)); return r;
}
__device__ __forceinline__ void fma2(u64& d, u64 a, u64 b) {
    asm("fma.rn.f32x2 %0, %1, %2, %0;" : "+l"(d) : "l"(a), "l"(b));
}
__device__ __forceinline__ float2 upk(u64 v) {
    float2 r; asm("mov.b64 {%0, %1}, %2;" : "=f"(r.x), "=f"(r.y) : "l"(v)); return r;
}

// ---------------- generic NT GEMM with FFMA2 ---------------------------------
// MODE 0: q = outs @ Win[0:E]^T + b, *0.125 -> g_q [B,H,T,D]
// MODE 1: kv = gs @ Win[E:3E]^T + b  (N=1536) -> g_k / g_v [B,H,S,D]
// MODE 3: e = exp(q@k^T + amask [pmask -> 0]) -> g_L; atomicAdd rowsum -> g_z
// MODE 4: O = (e @ v) * rz  per (b,h) slice -> g_attn [T,B,E]  (B transposed in-smem)
// MODE 5: x = g_attn @ Wout^T + b_out -> Cout
template <int MODE, int BM, int BN, int THREADS>
__global__ __launch_bounds__(THREADS, 2)
void gemm_k(const float* __restrict__ A, const float* __restrict__ Bw,
            const float* __restrict__ bias, float* __restrict__ Cout,
            const float* __restrict__ amask, const unsigned char* __restrict__ pmask)
{
    constexpr int K   = (MODE == 3) ? cD : ((MODE == 4) ? cS : cE);
    constexpr int BK  = 8;
    constexpr int AF4 = BM * BK / 4 / THREADS;
    constexpr int BF4 = BN * BK / 4 / THREADS;
    constexpr int CW  = BN / 8;

    const int zb = blockIdx.z;
    const float* Ap; const float* Bp;
    if constexpr (MODE == 0 || MODE == 1) { Ap = A;                            Bp = Bw; }
    else if constexpr (MODE == 3)         { Ap = g_q + zb * (cT * cD);         Bp = g_k + zb * (cS * cD); }
    else if constexpr (MODE == 4)         { Ap = g_L + (size_t)zb * cT * cS;   Bp = g_v + zb * (cS * cD); }
    else                                  { Ap = g_attn;                       Bp = Bw; }

    __shared__ float As[2][BK][BM];
    __shared__ float Bs[2][BK][BN];

    const int tid = threadIdx.x;
    const int m0 = blockIdx.y * BM;
    const int n0 = blockIdx.x * BN;
    const int rowg = tid / CW, colg = tid % CW;
    const int tm0 = rowg * 8, tn0 = colg * 8;

    u64 acc[4][8];
#pragma unroll
    for (int i = 0; i < 4; i++)
#pragma unroll
        for (int j = 0; j < 8; j++) acc[i][j] = 0ull;

    float4 pa[AF4], pb[BF4];

    auto loadT = [&](int k0) {
#pragma unroll
        for (int t = 0; t < AF4; t++) {
            const int idx = tid + t * THREADS;
            const int r = idx / (BK / 4), kc = (idx % (BK / 4)) * 4;
            pa[t] = *(const float4*)(Ap + (size_t)(m0 + r) * K + k0 + kc);
        }
        if constexpr (MODE == 4) {
            // B = v[s,d] (ldv = cD): load [BK s-rows x BN d-cols], transpose into Bs
#pragma unroll
            for (int t = 0; t < BF4; t++) {
                const int idx = tid + t * THREADS;
                const int dr = idx % (BN / 4), sr = idx / (BN / 4);
                pb[t] = *(const float4*)(Bp + (size_t)(k0 + sr) * cD + n0 + dr * 4);
            }
        } else {
#pragma unroll
            for (int t = 0; t < BF4; t++) {
                const int idx = tid + t * THREADS;
                const int r = idx / (BK / 4), kc = (idx % (BK / 4)) * 4;
                pb[t] = *(const float4*)(Bp + (size_t)(n0 + r) * K + k0 + kc);
            }
        }
    };
    auto storeS = [&](int buf) {
#pragma unroll
        for (int t = 0; t < AF4; t++) {
            const int idx = tid + t * THREADS;
            const int r = idx / (BK / 4), kc = (idx % (BK / 4)) * 4;
            As[buf][kc + 0][r] = pa[t].x; As[buf][kc + 1][r] = pa[t].y;
            As[buf][kc + 2][r] = pa[t].z; As[buf][kc + 3][r] = pa[t].w;
        }
        if constexpr (MODE == 4) {
#pragma unroll
            for (int t = 0; t < BF4; t++) {
                const int idx = tid + t * THREADS;
                const int dr = idx % (BN / 4), sr = idx / (BN / 4);
                Bs[buf][sr][dr * 4 + 0] = pb[t].x; Bs[buf][sr][dr * 4 + 1] = pb[t].y;
                Bs[buf][sr][dr * 4 + 2] = pb[t].z; Bs[buf][sr][dr * 4 + 3] = pb[t].w;
            }
        } else {
#pragma unroll
            for (int t = 0; t < BF4; t++) {
                const int idx = tid + t * THREADS;
                const int r = idx / (BK / 4), kc = (idx % (BK / 4)) * 4;
                Bs[buf][kc + 0][r] = pb[t].x; Bs[buf][kc + 1][r] = pb[t].y;
                Bs[buf][kc + 2][r] = pb[t].z; Bs[buf][kc + 3][r] = pb[t].w;
            }
        }
    };
    auto compute = [&](int buf) {
#pragma unroll
        for (int kk = 0; kk < BK; kk++) {
            const float4 av0 = *(const float4*)&As[buf][kk][tm0];
            const float4 av1 = *(const float4*)&As[buf][kk][tm0 + 4];
            const float4 bv0 = *(const float4*)&Bs[buf][kk][tn0];
            const float4 bv1 = *(const float4*)&Bs[buf][kk][tn0 + 4];
            const u64 a2[4] = { pk(av0.x, av0.y), pk(av0.z, av0.w),
                                pk(av1.x, av1.y), pk(av1.z, av1.w) };
            const u64 bb[8] = { pk1(bv0.x), pk1(bv0.y), pk1(bv0.z), pk1(bv0.w),
                                pk1(bv1.x), pk1(bv1.y), pk1(bv1.z), pk1(bv1.w) };
#pragma unroll
            for (int ip = 0; ip < 4; ip++)
#pragma unroll
                for (int j = 0; j < 8; j++) fma2(acc[ip][j], a2[ip], bb[j]);
        }
    };

    loadT(0); storeS(0); __syncthreads();
    int buf = 0;
    for (int k0 = BK; k0 < K; k0 += BK) {
        loadT(k0);
        compute(buf);
        storeS(buf ^ 1);
        __syncthreads();
        buf ^= 1;
    }
    compute(buf);

    float c[8][8];
#pragma unroll
    for (int ip = 0; ip < 4; ip++)
#pragma unroll
        for (int j = 0; j < 8; j++) {
            const float2 t = upk(acc[ip][j]);
            c[2 * ip + 0][j] = t.x;
            c[2 * ip + 1][j] = t.y;
        }

    // ---------------- epilogues ----------------
    if constexpr (MODE == 0) {
        const float4 bs0 = *(const float4*)&bias[n0 + tn0];
        const float4 bs1 = *(const float4*)&bias[n0 + tn0 + 4];
        const int gn = n0 + tn0;
        const int h = gn >> 6, d = gn & 63;
#pragma unroll
        for (int i = 0; i < 8; i++) {
            const int gm = m0 + tm0 + i;
            const int t = gm >> 3, b = gm & 7;
            float4 o0, o1;
            o0.x = (c[i][0] + bs0.x) * 0.125f; o0.y = (c[i][1] + bs0.y) * 0.125f;
            o0.z = (c[i][2] + bs0.z) * 0.125f; o0.w = (c[i][3] + bs0.w) * 0.125f;
            o1.x = (c[i][4] + bs1.x) * 0.125f; o1.y = (c[i][5] + bs1.y) * 0.125f;
            o1.z = (c[i][6] + bs1.z) * 0.125f; o1.w = (c[i][7] + bs1.w) * 0.125f;
            float* dst = g_q + (((size_t)(b * cH + h) * cT + t) * cD) + d;
            *(float4*)dst = o0; *(float4*)(dst + 4) = o1;
        }
    } else if constexpr (MODE == 1) {
        const float4 bs0 = *(const float4*)&bias[n0 + tn0];
        const float4 bs1 = *(const float4*)&bias[n0 + tn0 + 4];
        const int gn = n0 + tn0;
        const bool isV = gn >= cE;
        const int g = isV ? gn - cE : gn;
        const int h = g >> 6, d = g & 63;
        float* base = isV ? g_v : g_k;
#pragma unroll
        for (int i = 0; i < 8; i++) {
            const int gm = m0 + tm0 + i;
            const int s = gm >> 3, b = gm & 7;
            float4 o0, o1;
            o0.x = c[i][0] + bs0.x; o0.y = c[i][1] + bs0.y;
            o0.z = c[i][2] + bs0.z; o0.w = c[i][3] + bs0.w;
            o1.x = c[i][4] + bs1.x; o1.y = c[i][5] + bs1.y;
            o1.z = c[i][6] + bs1.z; o1.w = c[i][7] + bs1.w;
            float* dst = base + (((size_t)(b * cH + h) * cS + s) * cD) + d;
            *(float4*)dst = o0; *(float4*)(dst + 4) = o1;
        }
    } else if constexpr (MODE == 3) {
        const int b = zb / cH;
        const u64 pm8 = *(const u64*)&pmask[(size_t)b * cS + n0 + tn0];
        float rsum[8];
#pragma unroll
        for (int i = 0; i < 8; i++) {
            const int gm = m0 + tm0 + i;
            const float4 am0 = *(const float4*)&amask[(size_t)gm * cS + n0 + tn0];
            const float4 am1 = *(const float4*)&amask[(size_t)gm * cS + n0 + tn0 + 4];
            const float am[8] = {am0.x, am0.y, am0.z, am0.w, am1.x, am1.y, am1.z, am1.w};
            float e[8];
            float rs = 0.f;
#pragma unroll
            for (int j = 0; j < 8; j++) {
                const bool msk = ((pm8 >> (8 * j)) & 255ull) != 0;
                e[j] = msk ? 0.f : __expf(c[i][j] + am[j]);
                rs += e[j];
            }
            rsum[i] = rs;
            float* dst = g_L + (size_t)zb * cT * cS + (size_t)gm * cS + n0 + tn0;
            *(float4*)dst       = make_float4(e[0], e[1], e[2], e[3]);
            *(float4*)(dst + 4) = make_float4(e[4], e[5], e[6], e[7]);
        }
#pragma unroll
        for (int i = 0; i < 8; i++) {
#pragma unroll
            for (int o = 8; o; o >>= 1)
                rsum[i] += __shfl_xor_sync(0xffffffffu, rsum[i], o);
        }
        if (colg == 0) {
#pragma unroll
            for (int i = 0; i < 8; i++)
                atomicAdd(&g_z[zb * cT + m0 + tm0 + i], rsum[i]);
        }
    } else if constexpr (MODE == 4) {
        const int b = zb / cH, h = zb % cH;
#pragma unroll
        for (int i = 0; i < 8; i++) {
            const int gm = m0 + tm0 + i;                 // t
            const float rz = 1.0f / g_z[zb * cT + gm];
            float4 o0, o1;
            o0.x = c[i][0] * rz; o0.y = c[i][1] * rz; o0.z = c[i][2] * rz; o0.w = c[i][3] * rz;
            o1.x = c[i][4] * rz; o1.y = c[i][5] * rz; o1.z = c[i][6] * rz; o1.w = c[i][7] * rz;
            float* dst = g_attn + ((size_t)gm * cB + b) * cE + h * cD + n0 + tn0;
            *(float4*)dst = o0; *(float4*)(dst + 4) = o1;
        }
    } else {  // MODE 5
        const float4 bs0 = *(const float4*)&bias[n0 + tn0];
        const float4 bs1 = *(const float4*)&bias[n0 + tn0 + 4];
#pragma unroll
        for (int i = 0; i < 8; i++) {
            const int gm = m0 + tm0 + i;
            float4 o0, o1;
            o0.x = c[i][0] + bs0.x; o0.y = c[i][1] + bs0.y;
            o0.z = c[i][2] + bs0.z; o0.w = c[i][3] + bs0.w;
            o1.x = c[i][4] + bs1.x; o1.y = c[i][5] + bs1.y;
            o1.z = c[i][6] + bs1.z; o1.w = c[i][7] + bs1.w;
            float* dst = Cout + (size_t)gm * cE + n0 + tn0;
            *(float4*)dst = o0; *(float4*)(dst + 4) = o1;
        }
    }
}

// ------- BCE from e-values: p = e * (1/z), head-max, sum -> atomicAdd out[b] --
__global__ __launch_bounds__(256)
void prob_bce_kernel(float* __restrict__ out, const int* __restrict__ target_rel,
                     const float* __restrict__ strategy)
{
    const int t = blockIdx.x, b = blockIdx.y;
    __shared__ float srz[cH];
    if (threadIdx.x < cH)
        srz[threadIdx.x] = 1.0f / g_z[(b * cH + threadIdx.x) * cT + t];
    __syncthreads();

    float lsum = 0.f;
    for (int s = threadIdx.x; s < cS; s += 256) {
        float aw = 0.f;
#pragma unroll
        for (int h = 0; h < cH; h++) {
            const size_t idx = ((size_t)(b * cH + h) * cT + t) * cS + s;
            aw = fmaxf(aw, g_L[idx] * srz[h]);
        }
        const int rel = target_rel[(t * cB + b) * cS + s];
        if (rel != 0) {
            if (rel != 2) lsum += -fmaxf(logf(aw), -100.f);
            else          lsum += -fmaxf(log1pf(-aw), -100.f);
        }
    }
#pragma unroll
    for (int o = 16; o; o >>= 1) lsum += __shfl_xor_sync(0xffffffffu, lsum, o);
    __shared__ float wsum[8];
    if ((threadIdx.x & 31) == 0) wsum[threadIdx.x >> 5] = lsum;
    __syncthreads();
    if (threadIdx.x == 0) {
        float tot = 0.f;
#pragma unroll
        for (int w = 0; w < 8; w++) tot += wsum[w];
        atomicAdd(&out[b], tot * strategy[b]);
    }
}

// ---------------- small helpers ----------------------------------------------
__global__ void zero_loss(float* out)
{
    if (threadIdx.x < cB) out[threadIdx.x] = 0.f;
}
__global__ __launch_bounds__(256)
void zero_z_kernel()
{
    const int i = blockIdx.x * 256 + threadIdx.x;
    if (i < cB * cH * cT) g_z[i] = 0.f;
}
__global__ __launch_bounds__(256)
void copy_outs_kernel(float* __restrict__ dst, const float* __restrict__ src)
{
    const int i = blockIdx.x * 256 + threadIdx.x;
    ((float4*)dst)[i] = ((const float4*)src)[i];
}

// ---------------- entry point -------------------------------------------------
extern "C" void kernel_launch(void* const* d_in, const int* in_sizes, int n_in,
                              void* d_out, int out_size)
{
    const float*         outs   = (const float*)d_in[2];
    const float*         gstate = (const float*)d_in[3];
    const unsigned char* pmask  = (const unsigned char*)d_in[4];
    const float*         amask  = (const float*)d_in[5];
    const float*         strat  = (const float*)d_in[6];
    const int*           trel   = (const int*)d_in[7];
    const float*         Win    = (const float*)d_in[8];
    const float*         b_in   = (const float*)d_in[9];
    const float*         Wout   = (const float*)d_in[10];
    const float*         b_out  = (const float*)d_in[11];
    float* out = (float*)d_out;

    float* out_loss = out;
    float* out_copy = out + cB;
    float* out_x    = out + cB + (size_t)cT * cB * cE;

    zero_loss<<<1, 32>>>(out_loss);
    zero_z_kernel<<<(cB * cH * cT + 255) / 256, 256>>>();
    copy_outs_kernel<<<(cT * cB * cE / 4) / 256, 256>>>(out_copy, outs);

    // MODE 0: Q projection  [8192 x 768] x [768 x 768]
    gemm_k<0, 128, 128, 256><<<dim3(cE / 128, cT * cB / 128, 1), 256>>>(
        outs, Win, b_in, nullptr, nullptr, nullptr);
    // MODE 1: K+V fused     [8192 x 1536]
    gemm_k<1, 128, 128, 256><<<dim3(2 * cE / 128, cS * cB / 128, 1), 256>>>(
        gstate, Win + cE * cE, b_in + cE, nullptr, nullptr, nullptr);
    // MODE 3: logits -> e, rowsums (96 slices of 1024x1024x64)
    gemm_k<3, 128, 128, 256><<<dim3(cS / 128, cT / 128, cB * cH), 256>>>(
        nullptr, nullptr, nullptr, nullptr, amask, pmask);
    // BCE (reads e + z)
    prob_bce_kernel<<<dim3(cT, cB), 256>>>(out_loss, trel, strat);
    // MODE 4: O = softmax(e) @ V  (96 slices of 1024x64x1024)
    gemm_k<4, 128, 64, 128><<<dim3(1, cT / 128, cB * cH), 128>>>(
        nullptr, nullptr, nullptr, nullptr, nullptr, nullptr);
    // MODE 5: out projection
    gemm_k<5, 128, 128, 256><<<dim3(cE / 128, cT * cB / 128, 1), 256>>>(
        nullptr, Wout, b_out, out_x, nullptr, nullptr);
}

// round 7
// speedup vs baseline: 1.3117x; 1.3117x over previous
#include <cuda_runtime.h>
#include <cuda_bf16.h>
#include <math.h>
#include <stdint.h>

constexpr int cB = 8, cE = 768, cH = 12;
constexpr int ZS = cB * cH;          // 96 (b,h) slices
using bf = __nv_bfloat16;

// ---------------- device-global scratch (bf16 hi/lo pairs) -------------------
#define DARR(n, sz) __device__ __align__(16) bf n[sz]
DARR(c_outs_hi, 8192 * 768); DARR(c_outs_lo, 8192 * 768);
DARR(c_gs_hi,   8192 * 768); DARR(c_gs_lo,   8192 * 768);
DARR(c_win_hi,  2304 * 768); DARR(c_win_lo,  2304 * 768);
DARR(c_wout_hi,  768 * 768); DARR(c_wout_lo,  768 * 768);
DARR(g_qh, ZS * 1024 * 64);  DARR(g_ql, ZS * 1024 * 64);   // [z][t][d]
DARR(g_kh, ZS * 1024 * 64);  DARR(g_kl, ZS * 1024 * 64);   // [z][s][d]
DARR(g_vh, ZS * 1024 * 64);  DARR(g_vl, ZS * 1024 * 64);   // [z][s][d]
DARR(g_eh, (size_t)ZS * 1024 * 1024);                      // [z][t][s]
DARR(g_el, (size_t)ZS * 1024 * 1024);
DARR(c_at_hi, 8192 * 768);   DARR(c_at_lo, 8192 * 768);    // [(t*8+b)][e]
__device__ float g_z[ZS * 1024];

// ---------------- helpers ----------------------------------------------------
__device__ __forceinline__ void mma_bf16(float* d, const uint32_t* a,
                                         uint32_t b0, uint32_t b1) {
    asm volatile(
        "mma.sync.aligned.m16n8k16.row.col.f32.bf16.bf16.f32 "
        "{%0,%1,%2,%3},{%4,%5,%6,%7},{%8,%9},{%0,%1,%2,%3};"
        : "+f"(d[0]), "+f"(d[1]), "+f"(d[2]), "+f"(d[3])
        : "r"(a[0]), "r"(a[1]), "r"(a[2]), "r"(a[3]), "r"(b0), "r"(b1));
}
__device__ __forceinline__ void split_store(bf* hi, bf* lo, float v0, float v1) {
    bf h0 = __float2bfloat16(v0), h1 = __float2bfloat16(v1);
    __nv_bfloat162 H, L;
    H.x = h0; H.y = h1;
    L.x = __float2bfloat16(v0 - __bfloat162float(h0));
    L.y = __float2bfloat16(v1 - __bfloat162float(h1));
    *(__nv_bfloat162*)hi = H;
    *(__nv_bfloat162*)lo = L;
}

// ---------------- unified mma GEMM -------------------------------------------
// C[m][n] = sum_k A[m][k] * B[n][k]   (3-pass bf16 hi/lo split, fp32 accum)
// MODE 0: q   = outs @ Wq^T  (+b)*0.125 -> g_q   [z][t][d]
// MODE 1: k,v = gs @ Wkv^T   (+b)       -> g_k / g_v [z][s][d]
// MODE 3: e   = exp(q@k^T + amask; pmask->0) -> g_e, rowsums -> g_z
// MODE 4: attn= (e @ v^T[d][s]) / z     -> c_at  [(t*8+b)][e]
// MODE 5: x   = attn @ Wout^T (+b)      -> Cout fp32
template <int MODE, int BM, int BN, int WM, int WN, int K>
__global__ __launch_bounds__(256)
void mma_gemm(const float* __restrict__ bias, float* __restrict__ Cout,
              const float* __restrict__ amask, const unsigned char* __restrict__ pmask)
{
    constexpr int MA = WM / 16, NA = WN / 8, NWX = BN / WN;
    constexpr int KC = K / 16;
    __shared__ __align__(16) bf sAh[2][BM * 16], sAl[2][BM * 16];
    __shared__ __align__(16) bf sBh[2][BN * 16], sBl[2][BN * 16];

    const int tid = threadIdx.x, wid = tid >> 5, lane = tid & 31;
    const int g = lane >> 2, tg = lane & 3;
    const int m0 = blockIdx.y * BM, n0 = blockIdx.x * BN, zb = blockIdx.z;
    const int wm0 = (wid / NWX) * WM, wn0 = (wid % NWX) * WN;

    const bf *pAh, *pAl, *pBh, *pBl;
    size_t lda, ldb;
    if constexpr (MODE == 0)      { pAh = c_outs_hi; pAl = c_outs_lo; pBh = c_win_hi; pBl = c_win_lo; lda = ldb = 768; }
    else if constexpr (MODE == 1) { pAh = c_gs_hi;   pAl = c_gs_lo;
                                    pBh = c_win_hi + 768 * 768; pBl = c_win_lo + 768 * 768; lda = ldb = 768; }
    else if constexpr (MODE == 3) { pAh = g_qh + zb * 65536; pAl = g_ql + zb * 65536;
                                    pBh = g_kh + zb * 65536; pBl = g_kl + zb * 65536; lda = ldb = 64; }
    else if constexpr (MODE == 4) { pAh = g_eh + (size_t)zb * 1048576; pAl = g_el + (size_t)zb * 1048576;
                                    pBh = g_vh + zb * 65536; pBl = g_vl + zb * 65536; lda = 1024; ldb = 64; }
    else                          { pAh = c_at_hi; pAl = c_at_lo; pBh = c_wout_hi; pBl = c_wout_lo; lda = ldb = 768; }

    uint4 ra_h, ra_l, rb_h, rb_l;
    uint2 r4_h, r4_l;

    auto ldA = [&](int k0) {
        const int r = tid >> 1, kc = (tid & 1) * 8;
        ra_h = *(const uint4*)(pAh + (size_t)(m0 + r) * lda + k0 + kc);
        ra_l = *(const uint4*)(pAl + (size_t)(m0 + r) * lda + k0 + kc);
    };
    auto stA = [&](int b_) {
        const int r = tid >> 1, kc = (tid & 1) * 8;
        *(uint4*)&sAh[b_][r * 16 + kc] = ra_h;
        *(uint4*)&sAl[b_][r * 16 + kc] = ra_l;
    };
    auto ldB = [&](int k0) {
        if constexpr (MODE == 4) {
            const int s = tid >> 4, d0 = (tid & 15) * 4;
            r4_h = *(const uint2*)(pBh + (size_t)(k0 + s) * 64 + d0);
            r4_l = *(const uint2*)(pBl + (size_t)(k0 + s) * 64 + d0);
        } else {
            const int r = tid >> 1, kc = (tid & 1) * 8;
            rb_h = *(const uint4*)(pBh + (size_t)(n0 + r) * ldb + k0 + kc);
            rb_l = *(const uint4*)(pBl + (size_t)(n0 + r) * ldb + k0 + kc);
        }
    };
    auto stB = [&](int b_) {
        if constexpr (MODE == 4) {          // transpose v[s][d] -> Bs[d][s]
            const int s = tid >> 4, d0 = (tid & 15) * 4;
            const bf* ph = (const bf*)&r4_h;
            const bf* pl = (const bf*)&r4_l;
#pragma unroll
            for (int j = 0; j < 4; j++) {
                sBh[b_][(d0 + j) * 16 + s] = ph[j];
                sBl[b_][(d0 + j) * 16 + s] = pl[j];
            }
        } else {
            const int r = tid >> 1, kc = (tid & 1) * 8;
            *(uint4*)&sBh[b_][r * 16 + kc] = rb_h;
            *(uint4*)&sBl[b_][r * 16 + kc] = rb_l;
        }
    };

    float acc[MA][NA][4];
#pragma unroll
    for (int i = 0; i < MA; i++)
#pragma unroll
        for (int j = 0; j < NA; j++)
#pragma unroll
            for (int u = 0; u < 4; u++) acc[i][j][u] = 0.f;

    auto comp = [&](int b_) {
        uint32_t afh[MA][4], afl[MA][4];
#pragma unroll
        for (int ma = 0; ma < MA; ma++) {
            const int r = wm0 + 16 * ma + g;
            afh[ma][0] = *(const uint32_t*)&sAh[b_][r * 16 + 2 * tg];
            afh[ma][1] = *(const uint32_t*)&sAh[b_][(r + 8) * 16 + 2 * tg];
            afh[ma][2] = *(const uint32_t*)&sAh[b_][r * 16 + 2 * tg + 8];
            afh[ma][3] = *(const uint32_t*)&sAh[b_][(r + 8) * 16 + 2 * tg + 8];
            afl[ma][0] = *(const uint32_t*)&sAl[b_][r * 16 + 2 * tg];
            afl[ma][1] = *(const uint32_t*)&sAl[b_][(r + 8) * 16 + 2 * tg];
            afl[ma][2] = *(const uint32_t*)&sAl[b_][r * 16 + 2 * tg + 8];
            afl[ma][3] = *(const uint32_t*)&sAl[b_][(r + 8) * 16 + 2 * tg + 8];
        }
#pragma unroll
        for (int na = 0; na < NA; na++) {
            const int c = wn0 + 8 * na + g;
            const uint32_t bh0 = *(const uint32_t*)&sBh[b_][c * 16 + 2 * tg];
            const uint32_t bh1 = *(const uint32_t*)&sBh[b_][c * 16 + 2 * tg + 8];
            const uint32_t bl0 = *(const uint32_t*)&sBl[b_][c * 16 + 2 * tg];
            const uint32_t bl1 = *(const uint32_t*)&sBl[b_][c * 16 + 2 * tg + 8];
#pragma unroll
            for (int ma = 0; ma < MA; ma++) {
                mma_bf16(acc[ma][na], afh[ma], bh0, bh1);
                mma_bf16(acc[ma][na], afh[ma], bl0, bl1);
                mma_bf16(acc[ma][na], afl[ma], bh0, bh1);
            }
        }
    };

    ldA(0); ldB(0); stA(0); stB(0); __syncthreads();
    int b_ = 0;
    for (int c = 1; c < KC; c++) {
        ldA(c * 16); ldB(c * 16);
        comp(b_);
        stA(b_ ^ 1); stB(b_ ^ 1);
        __syncthreads();
        b_ ^= 1;
    }
    comp(b_);

    // ---------------- epilogue ----------------
#pragma unroll
    for (int ma = 0; ma < MA; ma++) {
#pragma unroll
        for (int hf = 0; hf < 2; hf++) {
            const int gm = m0 + wm0 + 16 * ma + g + 8 * hf;
            float rsum = 0.f;
            float rz = 1.f;
            if constexpr (MODE == 4) rz = 1.f / g_z[zb * 1024 + gm];
#pragma unroll
            for (int na = 0; na < NA; na++) {
                const int c0 = n0 + wn0 + 8 * na + 2 * tg;
                float v0 = acc[ma][na][hf * 2], v1 = acc[ma][na][hf * 2 + 1];
                if constexpr (MODE == 0) {
                    v0 = (v0 + bias[c0]) * 0.125f;
                    v1 = (v1 + bias[c0 + 1]) * 0.125f;
                    const int t = gm >> 3, b = gm & 7, h = c0 >> 6, d = c0 & 63;
                    const size_t off = ((size_t)(b * cH + h) * 1024 + t) * 64 + d;
                    split_store(g_qh + off, g_ql + off, v0, v1);
                } else if constexpr (MODE == 1) {
                    v0 += bias[c0]; v1 += bias[c0 + 1];
                    const int s = gm >> 3, b = gm & 7;
                    const bool isV = c0 >= 768;
                    const int cc = isV ? c0 - 768 : c0;
                    const int h = cc >> 6, d = cc & 63;
                    const size_t off = ((size_t)(b * cH + h) * 1024 + s) * 64 + d;
                    if (isV) split_store(g_vh + off, g_vl + off, v0, v1);
                    else     split_store(g_kh + off, g_kl + off, v0, v1);
                } else if constexpr (MODE == 3) {
                    const int b = zb / cH;
                    const float a0 = amask[(size_t)gm * 1024 + c0];
                    const float a1 = amask[(size_t)gm * 1024 + c0 + 1];
                    const float e0 = pmask[b * 1024 + c0]     ? 0.f : __expf(v0 + a0);
                    const float e1 = pmask[b * 1024 + c0 + 1] ? 0.f : __expf(v1 + a1);
                    rsum += e0 + e1;
                    const size_t off = (size_t)zb * 1048576 + (size_t)gm * 1024 + c0;
                    split_store(g_eh + off, g_el + off, e0, e1);
                } else if constexpr (MODE == 4) {
                    const int b = zb / cH, h = zb % cH;
                    const size_t off = ((size_t)gm * 8 + b) * 768 + h * 64 + c0;
                    split_store(c_at_hi + off, c_at_lo + off, v0 * rz, v1 * rz);
                } else {
                    float2 o;
                    o.x = v0 + bias[c0]; o.y = v1 + bias[c0 + 1];
                    *(float2*)&Cout[(size_t)gm * 768 + c0] = o;
                }
            }
            if constexpr (MODE == 3) {
                rsum += __shfl_xor_sync(0xffffffffu, rsum, 1);
                rsum += __shfl_xor_sync(0xffffffffu, rsum, 2);
                if (tg == 0) atomicAdd(&g_z[zb * 1024 + gm], rsum);
            }
        }
    }
}

// ---------------- fp32 -> bf16 hi/lo conversions -----------------------------
template <int W>
__global__ __launch_bounds__(256)
void conv_split(const float* __restrict__ src, int npairs)
{
    bf *hi, *lo;
    if constexpr (W == 0)      { hi = c_outs_hi; lo = c_outs_lo; }
    else if constexpr (W == 1) { hi = c_gs_hi;   lo = c_gs_lo; }
    else if constexpr (W == 2) { hi = c_win_hi;  lo = c_win_lo; }
    else                       { hi = c_wout_hi; lo = c_wout_lo; }
    const int i = blockIdx.x * 256 + threadIdx.x;
    if (i >= npairs) return;
    const float2 v = ((const float2*)src)[i];
    split_store(hi + 2 * i, lo + 2 * i, v.x, v.y);
}

// ---------------- BCE --------------------------------------------------------
__global__ __launch_bounds__(256)
void bce_kernel(float* __restrict__ out, const int* __restrict__ trel,
                const float* __restrict__ strat)
{
    const int t = blockIdx.x, b = blockIdx.y;
    __shared__ float srz[cH];
    if (threadIdx.x < cH)
        srz[threadIdx.x] = 1.f / g_z[(b * cH + threadIdx.x) * 1024 + t];
    __syncthreads();
    float ls = 0.f;
    for (int sp = threadIdx.x; sp < 512; sp += 256) {
        float aw0 = 0.f, aw1 = 0.f;
#pragma unroll
        for (int h = 0; h < cH; h++) {
            const __nv_bfloat162 e2 = *(const __nv_bfloat162*)
                &g_eh[((size_t)(b * cH + h) * 1024 + t) * 1024 + 2 * sp];
            aw0 = fmaxf(aw0, __bfloat162float(e2.x) * srz[h]);
            aw1 = fmaxf(aw1, __bfloat162float(e2.y) * srz[h]);
        }
        const int2 rr = *(const int2*)&trel[((size_t)t * 8 + b) * 1024 + 2 * sp];
        if (rr.x) ls += (rr.x != 2) ? -fmaxf(logf(aw0), -100.f)
                                    : -fmaxf(log1pf(-aw0), -100.f);
        if (rr.y) ls += (rr.y != 2) ? -fmaxf(logf(aw1), -100.f)
                                    : -fmaxf(log1pf(-aw1), -100.f);
    }
#pragma unroll
    for (int o = 16; o; o >>= 1) ls += __shfl_xor_sync(0xffffffffu, ls, o);
    __shared__ float ws[8];
    if ((threadIdx.x & 31) == 0) ws[threadIdx.x >> 5] = ls;
    __syncthreads();
    if (threadIdx.x == 0) {
        float tot = 0.f;
#pragma unroll
        for (int w = 0; w < 8; w++) tot += ws[w];
        atomicAdd(&out[b], tot * strat[b]);
    }
}

// ---------------- helpers ----------------------------------------------------
__global__ void zero_loss(float* out) { if (threadIdx.x < cB) out[threadIdx.x] = 0.f; }
__global__ __launch_bounds__(256) void zero_z_kernel()
{
    const int i = blockIdx.x * 256 + threadIdx.x;
    if (i < ZS * 1024) g_z[i] = 0.f;
}
__global__ __launch_bounds__(256)
void copy_outs_kernel(float* __restrict__ dst, const float* __restrict__ src)
{
    const int i = blockIdx.x * 256 + threadIdx.x;
    ((float4*)dst)[i] = ((const float4*)src)[i];
}

// ---------------- entry point -------------------------------------------------
extern "C" void kernel_launch(void* const* d_in, const int* in_sizes, int n_in,
                              void* d_out, int out_size)
{
    const float*         outs   = (const float*)d_in[2];
    const float*         gstate = (const float*)d_in[3];
    const unsigned char* pmask  = (const unsigned char*)d_in[4];
    const float*         amask  = (const float*)d_in[5];
    const float*         strat  = (const float*)d_in[6];
    const int*           trel   = (const int*)d_in[7];
    const float*         b_in   = (const float*)d_in[9];
    const float*         b_out  = (const float*)d_in[11];
    float* out = (float*)d_out;

    float* out_loss = out;
    float* out_copy = out + cB;
    float* out_x    = out + cB + (size_t)1024 * cB * cE;

    zero_loss<<<1, 32>>>(out_loss);
    zero_z_kernel<<<ZS * 1024 / 256, 256>>>();
    copy_outs_kernel<<<(1024 * cB * cE / 4) / 256, 256>>>(out_copy, outs);

    conv_split<0><<<8192 * 768 / 2 / 256, 256>>>(outs,   8192 * 768 / 2);
    conv_split<1><<<8192 * 768 / 2 / 256, 256>>>(gstate, 8192 * 768 / 2);
    conv_split<2><<<2304 * 768 / 2 / 256, 256>>>((const float*)d_in[8],  2304 * 768 / 2);
    conv_split<3><<<768 * 768 / 2 / 256, 256>>>((const float*)d_in[10], 768 * 768 / 2);

    // MODE 0: Q projection
    mma_gemm<0, 128, 128, 64, 32, 768><<<dim3(6, 64, 1), 256>>>(b_in, nullptr, nullptr, nullptr);
    // MODE 1: K+V fused
    mma_gemm<1, 128, 128, 64, 32, 768><<<dim3(12, 64, 1), 256>>>(b_in + 768, nullptr, nullptr, nullptr);
    // MODE 3: logits -> e + rowsums
    mma_gemm<3, 128, 128, 64, 32, 64><<<dim3(8, 8, 96), 256>>>(nullptr, nullptr, amask, pmask);
    // BCE
    bce_kernel<<<dim3(1024, cB), 256>>>(out_loss, trel, strat);
    // MODE 4: attn = e @ v / z
    mma_gemm<4, 128, 64, 32, 32, 1024><<<dim3(1, 8, 96), 256>>>(nullptr, nullptr, nullptr, nullptr);
    // MODE 5: out projection
    mma_gemm<5, 128, 128, 64, 32, 768><<<dim3(6, 64, 1), 256>>>(b_out, out_x, nullptr, nullptr);
}

// round 8
// speedup vs baseline: 1.4341x; 1.0933x over previous
#include <cuda_runtime.h>
#include <cuda_fp16.h>
#include <math.h>
#include <stdint.h>

constexpr int cB = 8, cE = 768, cH = 12;
constexpr int ZS = cB * cH;          // 96 (b,h) slices
using hf = __half;

// ---------------- device-global scratch (fp16 hi/lo pairs) -------------------
#define DARR(n, sz) __device__ __align__(16) hf n[sz]
DARR(c_outs_hi, 8192 * 768); DARR(c_outs_lo, 8192 * 768);
DARR(c_gs_hi,   8192 * 768); DARR(c_gs_lo,   8192 * 768);
DARR(c_win_hi,  2304 * 768); DARR(c_win_lo,  2304 * 768);
DARR(c_wout_hi,  768 * 768); DARR(c_wout_lo,  768 * 768);
DARR(g_qh, ZS * 1024 * 64);  DARR(g_ql, ZS * 1024 * 64);   // [z][t][d]
DARR(g_kh, ZS * 1024 * 64);  DARR(g_kl, ZS * 1024 * 64);   // [z][s][d]
DARR(g_vh, ZS * 1024 * 64);  DARR(g_vl, ZS * 1024 * 64);   // [z][s][d]
DARR(g_e,  (size_t)ZS * 1024 * 1024);                      // [z][t][s] fp16 (no lo)
DARR(c_at_hi, 8192 * 768);   DARR(c_at_lo, 8192 * 768);    // [(t*8+b)][e]
__device__ float g_z[ZS * 1024];

// ---------------- helpers ----------------------------------------------------
__device__ __forceinline__ void mma_f16(float* d, const uint32_t* a,
                                        uint32_t b0, uint32_t b1) {
    asm volatile(
        "mma.sync.aligned.m16n8k16.row.col.f32.f16.f16.f32 "
        "{%0,%1,%2,%3},{%4,%5,%6,%7},{%8,%9},{%0,%1,%2,%3};"
        : "+f"(d[0]), "+f"(d[1]), "+f"(d[2]), "+f"(d[3])
        : "r"(a[0]), "r"(a[1]), "r"(a[2]), "r"(a[3]), "r"(b0), "r"(b1));
}
__device__ __forceinline__ void split_store(hf* hi, hf* lo, float v0, float v1) {
    const hf h0 = __float2half_rn(v0), h1 = __float2half_rn(v1);
    __half2 H, L;
    H.x = h0; H.y = h1;
    L.x = __float2half_rn(v0 - __half2float(h0));
    L.y = __float2half_rn(v1 - __half2float(h1));
    *(__half2*)hi = H;
    *(__half2*)lo = L;
}

// ---------------- unified mma GEMM -------------------------------------------
// C[m][n] = sum_k A[m][k] * B[n][k]   (fp16 hi/lo split, fp32 accum)
// passes: Ah*Bh + Ah*Bl (+ Al*Bh when A is split)
// MODE 0: q   = outs @ Wq^T  (+b)*0.125 -> g_q   [z][t][d]
// MODE 1: k,v = gs @ Wkv^T   (+b)       -> g_k / g_v [z][s][d]
// MODE 3: e   = exp(q@k^T + amask; pmask->0) -> g_e (fp16), rowsums -> g_z
// MODE 4: attn= (e @ v^T) / z           -> c_at  [(t*8+b)][e]   (A = e, no lo)
// MODE 5: x   = attn @ Wout^T (+b)      -> Cout fp32
template <int MODE, int BM, int BN, int WM, int WN, int K>
__global__ __launch_bounds__(256)
void mma_gemm(const float* __restrict__ bias, float* __restrict__ Cout,
              const float* __restrict__ amask, const unsigned char* __restrict__ pmask)
{
    constexpr int MA = WM / 16, NA = WN / 8, NWX = BN / WN;
    constexpr int KC = K / 16;
    constexpr bool ALO = (MODE != 4);          // A has a lo component
    __shared__ __align__(16) hf sAh[2][BM * 16];
    __shared__ __align__(16) hf sAl[ALO ? 2 : 1][ALO ? BM * 16 : 8];
    __shared__ __align__(16) hf sBh[2][BN * 16], sBl[2][BN * 16];

    const int tid = threadIdx.x, wid = tid >> 5, lane = tid & 31;
    const int g = lane >> 2, tg = lane & 3;
    const int m0 = blockIdx.y * BM, n0 = blockIdx.x * BN, zb = blockIdx.z;
    const int wm0 = (wid / NWX) * WM, wn0 = (wid % NWX) * WN;

    const hf *pAh, *pAl, *pBh, *pBl;
    size_t lda, ldb;
    if constexpr (MODE == 0)      { pAh = c_outs_hi; pAl = c_outs_lo; pBh = c_win_hi; pBl = c_win_lo; lda = ldb = 768; }
    else if constexpr (MODE == 1) { pAh = c_gs_hi;   pAl = c_gs_lo;
                                    pBh = c_win_hi + 768 * 768; pBl = c_win_lo + 768 * 768; lda = ldb = 768; }
    else if constexpr (MODE == 3) { pAh = g_qh + zb * 65536; pAl = g_ql + zb * 65536;
                                    pBh = g_kh + zb * 65536; pBl = g_kl + zb * 65536; lda = ldb = 64; }
    else if constexpr (MODE == 4) { pAh = g_e + (size_t)zb * 1048576; pAl = nullptr;
                                    pBh = g_vh + zb * 65536; pBl = g_vl + zb * 65536; lda = 1024; ldb = 64; }
    else                          { pAh = c_at_hi; pAl = c_at_lo; pBh = c_wout_hi; pBl = c_wout_lo; lda = ldb = 768; }

    uint4 ra_h, ra_l, rb_h, rb_l;
    uint2 r4_h, r4_l;

    auto ldA = [&](int k0) {
        const int r = tid >> 1, kc = (tid & 1) * 8;
        ra_h = *(const uint4*)(pAh + (size_t)(m0 + r) * lda + k0 + kc);
        if constexpr (ALO)
            ra_l = *(const uint4*)(pAl + (size_t)(m0 + r) * lda + k0 + kc);
    };
    auto stA = [&](int b_) {
        const int r = tid >> 1, kc = (tid & 1) * 8;
        *(uint4*)&sAh[b_][r * 16 + kc] = ra_h;
        if constexpr (ALO)
            *(uint4*)&sAl[b_][r * 16 + kc] = ra_l;
    };
    auto ldB = [&](int k0) {
        if constexpr (MODE == 4) {
            const int s = tid >> 4, d0 = (tid & 15) * 4;
            r4_h = *(const uint2*)(pBh + (size_t)(k0 + s) * 64 + d0);
            r4_l = *(const uint2*)(pBl + (size_t)(k0 + s) * 64 + d0);
        } else {
            const int r = tid >> 1, kc = (tid & 1) * 8;
            rb_h = *(const uint4*)(pBh + (size_t)(n0 + r) * ldb + k0 + kc);
            rb_l = *(const uint4*)(pBl + (size_t)(n0 + r) * ldb + k0 + kc);
        }
    };
    auto stB = [&](int b_) {
        if constexpr (MODE == 4) {          // transpose v[s][d] -> Bs[d][s]
            const int s = tid >> 4, d0 = (tid & 15) * 4;
            const hf* ph = (const hf*)&r4_h;
            const hf* pl = (const hf*)&r4_l;
#pragma unroll
            for (int j = 0; j < 4; j++) {
                sBh[b_][(d0 + j) * 16 + s] = ph[j];
                sBl[b_][(d0 + j) * 16 + s] = pl[j];
            }
        } else {
            const int r = tid >> 1, kc = (tid & 1) * 8;
            *(uint4*)&sBh[b_][r * 16 + kc] = rb_h;
            *(uint4*)&sBl[b_][r * 16 + kc] = rb_l;
        }
    };

    float acc[MA][NA][4];
#pragma unroll
    for (int i = 0; i < MA; i++)
#pragma unroll
        for (int j = 0; j < NA; j++)
#pragma unroll
            for (int u = 0; u < 4; u++) acc[i][j][u] = 0.f;

    auto comp = [&](int b_) {
        uint32_t afh[MA][4], afl[MA][4];
#pragma unroll
        for (int ma = 0; ma < MA; ma++) {
            const int r = wm0 + 16 * ma + g;
            afh[ma][0] = *(const uint32_t*)&sAh[b_][r * 16 + 2 * tg];
            afh[ma][1] = *(const uint32_t*)&sAh[b_][(r + 8) * 16 + 2 * tg];
            afh[ma][2] = *(const uint32_t*)&sAh[b_][r * 16 + 2 * tg + 8];
            afh[ma][3] = *(const uint32_t*)&sAh[b_][(r + 8) * 16 + 2 * tg + 8];
            if constexpr (ALO) {
                afl[ma][0] = *(const uint32_t*)&sAl[b_][r * 16 + 2 * tg];
                afl[ma][1] = *(const uint32_t*)&sAl[b_][(r + 8) * 16 + 2 * tg];
                afl[ma][2] = *(const uint32_t*)&sAl[b_][r * 16 + 2 * tg + 8];
                afl[ma][3] = *(const uint32_t*)&sAl[b_][(r + 8) * 16 + 2 * tg + 8];
            }
        }
#pragma unroll
        for (int na = 0; na < NA; na++) {
            const int c = wn0 + 8 * na + g;
            const uint32_t bh0 = *(const uint32_t*)&sBh[b_][c * 16 + 2 * tg];
            const uint32_t bh1 = *(const uint32_t*)&sBh[b_][c * 16 + 2 * tg + 8];
            const uint32_t bl0 = *(const uint32_t*)&sBl[b_][c * 16 + 2 * tg];
            const uint32_t bl1 = *(const uint32_t*)&sBl[b_][c * 16 + 2 * tg + 8];
#pragma unroll
            for (int ma = 0; ma < MA; ma++) {
                mma_f16(acc[ma][na], afh[ma], bh0, bh1);
                mma_f16(acc[ma][na], afh[ma], bl0, bl1);
                if constexpr (ALO) mma_f16(acc[ma][na], afl[ma], bh0, bh1);
            }
        }
    };

    ldA(0); ldB(0); stA(0); stB(0); __syncthreads();
    int b_ = 0;
    for (int c = 1; c < KC; c++) {
        ldA(c * 16); ldB(c * 16);
        comp(b_);
        stA(b_ ^ 1); stB(b_ ^ 1);
        __syncthreads();
        b_ ^= 1;
    }
    comp(b_);

    // ---------------- epilogue ----------------
#pragma unroll
    for (int ma = 0; ma < MA; ma++) {
#pragma unroll
        for (int hfi = 0; hfi < 2; hfi++) {
            const int gm = m0 + wm0 + 16 * ma + g + 8 * hfi;
            float rsum = 0.f;
            float rz = 1.f;
            if constexpr (MODE == 4) rz = 1.f / g_z[zb * 1024 + gm];
#pragma unroll
            for (int na = 0; na < NA; na++) {
                const int c0 = n0 + wn0 + 8 * na + 2 * tg;
                float v0 = acc[ma][na][hfi * 2], v1 = acc[ma][na][hfi * 2 + 1];
                if constexpr (MODE == 0) {
                    v0 = (v0 + bias[c0]) * 0.125f;
                    v1 = (v1 + bias[c0 + 1]) * 0.125f;
                    const int t = gm >> 3, b = gm & 7, h = c0 >> 6, d = c0 & 63;
                    const size_t off = ((size_t)(b * cH + h) * 1024 + t) * 64 + d;
                    split_store(g_qh + off, g_ql + off, v0, v1);
                } else if constexpr (MODE == 1) {
                    v0 += bias[c0]; v1 += bias[c0 + 1];
                    const int s = gm >> 3, b = gm & 7;
                    const bool isV = c0 >= 768;
                    const int cc = isV ? c0 - 768 : c0;
                    const int h = cc >> 6, d = cc & 63;
                    const size_t off = ((size_t)(b * cH + h) * 1024 + s) * 64 + d;
                    if (isV) split_store(g_vh + off, g_vl + off, v0, v1);
                    else     split_store(g_kh + off, g_kl + off, v0, v1);
                } else if constexpr (MODE == 3) {
                    const int b = zb / cH;
                    const float a0 = amask[(size_t)gm * 1024 + c0];
                    const float a1 = amask[(size_t)gm * 1024 + c0 + 1];
                    const float e0 = pmask[b * 1024 + c0]     ? 0.f : __expf(v0 + a0);
                    const float e1 = pmask[b * 1024 + c0 + 1] ? 0.f : __expf(v1 + a1);
                    rsum += e0 + e1;
                    __half2 E; E.x = __float2half_rn(e0); E.y = __float2half_rn(e1);
                    *(__half2*)&g_e[(size_t)zb * 1048576 + (size_t)gm * 1024 + c0] = E;
                } else if constexpr (MODE == 4) {
                    const int b = zb / cH, h = zb % cH;
                    const size_t off = ((size_t)gm * 8 + b) * 768 + h * 64 + c0;
                    split_store(c_at_hi + off, c_at_lo + off, v0 * rz, v1 * rz);
                } else {
                    float2 o;
                    o.x = v0 + bias[c0]; o.y = v1 + bias[c0 + 1];
                    *(float2*)&Cout[(size_t)gm * 768 + c0] = o;
                }
            }
            if constexpr (MODE == 3) {
                rsum += __shfl_xor_sync(0xffffffffu, rsum, 1);
                rsum += __shfl_xor_sync(0xffffffffu, rsum, 2);
                if (tg == 0) atomicAdd(&g_z[zb * 1024 + gm], rsum);
            }
        }
    }
}

// ---------------- fp32 -> fp16 hi/lo conversions -----------------------------
template <int W>
__global__ __launch_bounds__(256)
void conv_split(const float* __restrict__ src, int npairs)
{
    hf *hi, *lo;
    if constexpr (W == 0)      { hi = c_outs_hi; lo = c_outs_lo; }
    else if constexpr (W == 1) { hi = c_gs_hi;   lo = c_gs_lo; }
    else if constexpr (W == 2) { hi = c_win_hi;  lo = c_win_lo; }
    else                       { hi = c_wout_hi; lo = c_wout_lo; }
    const int i = blockIdx.x * 256 + threadIdx.x;
    if (i >= npairs) return;
    const float2 v = ((const float2*)src)[i];
    split_store(hi + 2 * i, lo + 2 * i, v.x, v.y);
}

// ---------------- BCE --------------------------------------------------------
__global__ __launch_bounds__(256)
void bce_kernel(float* __restrict__ out, const int* __restrict__ trel,
                const float* __restrict__ strat)
{
    const int t = blockIdx.x, b = blockIdx.y;
    __shared__ float srz[cH];
    if (threadIdx.x < cH)
        srz[threadIdx.x] = 1.f / g_z[(b * cH + threadIdx.x) * 1024 + t];
    __syncthreads();
    float ls = 0.f;
    for (int sp = threadIdx.x; sp < 512; sp += 256) {
        float aw0 = 0.f, aw1 = 0.f;
#pragma unroll
        for (int h = 0; h < cH; h++) {
            const __half2 e2 = *(const __half2*)
                &g_e[((size_t)(b * cH + h) * 1024 + t) * 1024 + 2 * sp];
            aw0 = fmaxf(aw0, __half2float(e2.x) * srz[h]);
            aw1 = fmaxf(aw1, __half2float(e2.y) * srz[h]);
        }
        const int2 rr = *(const int2*)&trel[((size_t)t * 8 + b) * 1024 + 2 * sp];
        if (rr.x) ls += (rr.x != 2) ? -fmaxf(logf(aw0), -100.f)
                                    : -fmaxf(log1pf(-aw0), -100.f);
        if (rr.y) ls += (rr.y != 2) ? -fmaxf(logf(aw1), -100.f)
                                    : -fmaxf(log1pf(-aw1), -100.f);
    }
#pragma unroll
    for (int o = 16; o; o >>= 1) ls += __shfl_xor_sync(0xffffffffu, ls, o);
    __shared__ float ws[8];
    if ((threadIdx.x & 31) == 0) ws[threadIdx.x >> 5] = ls;
    __syncthreads();
    if (threadIdx.x == 0) {
        float tot = 0.f;
#pragma unroll
        for (int w = 0; w < 8; w++) tot += ws[w];
        atomicAdd(&out[b], tot * strat[b]);
    }
}

// ---------------- helpers ----------------------------------------------------
__global__ void zero_loss(float* out) { if (threadIdx.x < cB) out[threadIdx.x] = 0.f; }
__global__ __launch_bounds__(256) void zero_z_kernel()
{
    const int i = blockIdx.x * 256 + threadIdx.x;
    if (i < ZS * 1024) g_z[i] = 0.f;
}
__global__ __launch_bounds__(256)
void copy_outs_kernel(float* __restrict__ dst, const float* __restrict__ src)
{
    const int i = blockIdx.x * 256 + threadIdx.x;
    ((float4*)dst)[i] = ((const float4*)src)[i];
}

// ---------------- entry point -------------------------------------------------
extern "C" void kernel_launch(void* const* d_in, const int* in_sizes, int n_in,
                              void* d_out, int out_size)
{
    const float*         outs   = (const float*)d_in[2];
    const float*         gstate = (const float*)d_in[3];
    const unsigned char* pmask  = (const unsigned char*)d_in[4];
    const float*         amask  = (const float*)d_in[5];
    const float*         strat  = (const float*)d_in[6];
    const int*           trel   = (const int*)d_in[7];
    const float*         b_in   = (const float*)d_in[9];
    const float*         b_out  = (const float*)d_in[11];
    float* out = (float*)d_out;

    float* out_loss = out;
    float* out_copy = out + cB;
    float* out_x    = out + cB + (size_t)1024 * cB * cE;

    zero_loss<<<1, 32>>>(out_loss);
    zero_z_kernel<<<ZS * 1024 / 256, 256>>>();
    copy_outs_kernel<<<(1024 * cB * cE / 4) / 256, 256>>>(out_copy, outs);

    conv_split<0><<<8192 * 768 / 2 / 256, 256>>>(outs,   8192 * 768 / 2);
    conv_split<1><<<8192 * 768 / 2 / 256, 256>>>(gstate, 8192 * 768 / 2);
    conv_split<2><<<2304 * 768 / 2 / 256, 256>>>((const float*)d_in[8],  2304 * 768 / 2);
    conv_split<3><<<768 * 768 / 2 / 256, 256>>>((const float*)d_in[10], 768 * 768 / 2);

    // MODE 0: Q projection
    mma_gemm<0, 128, 128, 64, 32, 768><<<dim3(6, 64, 1), 256>>>(b_in, nullptr, nullptr, nullptr);
    // MODE 1: K+V fused
    mma_gemm<1, 128, 128, 64, 32, 768><<<dim3(12, 64, 1), 256>>>(b_in + 768, nullptr, nullptr, nullptr);
    // MODE 3: logits -> e + rowsums
    mma_gemm<3, 128, 128, 64, 32, 64><<<dim3(8, 8, 96), 256>>>(nullptr, nullptr, amask, pmask);
    // BCE
    bce_kernel<<<dim3(1024, cB), 256>>>(out_loss, trel, strat);
    // MODE 4: attn = e @ v / z
    mma_gemm<4, 128, 64, 32, 32, 1024><<<dim3(1, 8, 96), 256>>>(nullptr, nullptr, nullptr, nullptr);
    // MODE 5: out projection
    mma_gemm<5, 128, 128, 64, 32, 768><<<dim3(6, 64, 1), 256>>>(b_out, out_x, nullptr, nullptr);
}

// round 9
// speedup vs baseline: 1.5937x; 1.1113x over previous
#include <cuda_runtime.h>
#include <cuda_fp16.h>
#include <math.h>
#include <stdint.h>

constexpr int cB = 8, cE = 768, cH = 12;
constexpr int ZS = cB * cH;          // 96 (b,h) slices
using hf = __half;

// ---------------- device-global scratch (fp16 hi/lo pairs) -------------------
#define DARR(n, sz) __device__ __align__(16) hf n[sz]
DARR(c_outs_hi, 8192 * 768); DARR(c_outs_lo, 8192 * 768);
DARR(c_gs_hi,   8192 * 768); DARR(c_gs_lo,   8192 * 768);
DARR(c_win_hi,  2304 * 768); DARR(c_win_lo,  2304 * 768);
DARR(c_wout_hi,  768 * 768); DARR(c_wout_lo,  768 * 768);
DARR(g_qh, ZS * 1024 * 64);  DARR(g_ql, ZS * 1024 * 64);   // [z][t][d]
DARR(g_kh, ZS * 1024 * 64);  DARR(g_kl, ZS * 1024 * 64);   // [z][s][d]
DARR(g_vh, ZS * 1024 * 64);  DARR(g_vl, ZS * 1024 * 64);   // [z][s][d]
DARR(g_e,  (size_t)ZS * 1024 * 1024);                      // [z][t][s] fp16 (no lo)
DARR(c_at_hi, 8192 * 768);   DARR(c_at_lo, 8192 * 768);    // [(t*8+b)][e]
__device__ float g_z[ZS * 1024];

// ---------------- helpers ----------------------------------------------------
__device__ __forceinline__ void mma_f16(float* d, const uint32_t* a,
                                        uint32_t b0, uint32_t b1) {
    asm volatile(
        "mma.sync.aligned.m16n8k16.row.col.f32.f16.f16.f32 "
        "{%0,%1,%2,%3},{%4,%5,%6,%7},{%8,%9},{%0,%1,%2,%3};"
        : "+f"(d[0]), "+f"(d[1]), "+f"(d[2]), "+f"(d[3])
        : "r"(a[0]), "r"(a[1]), "r"(a[2]), "r"(a[3]), "r"(b0), "r"(b1));
}
__device__ __forceinline__ uint32_t s2u(const void* p) {
    return (uint32_t)__cvta_generic_to_shared(p);
}
__device__ __forceinline__ void ldsm4(uint32_t& a, uint32_t& b, uint32_t& c,
                                      uint32_t& d, uint32_t addr) {
    asm volatile("ldmatrix.sync.aligned.m8n8.x4.shared.b16 {%0,%1,%2,%3}, [%4];"
                 : "=r"(a), "=r"(b), "=r"(c), "=r"(d) : "r"(addr));
}
__device__ __forceinline__ void ldsm4t(uint32_t& a, uint32_t& b, uint32_t& c,
                                       uint32_t& d, uint32_t addr) {
    asm volatile("ldmatrix.sync.aligned.m8n8.x4.trans.shared.b16 {%0,%1,%2,%3}, [%4];"
                 : "=r"(a), "=r"(b), "=r"(c), "=r"(d) : "r"(addr));
}
__device__ __forceinline__ void split_store(hf* hi, hf* lo, float v0, float v1) {
    const hf h0 = __float2half_rn(v0), h1 = __float2half_rn(v1);
    __half2 H, L;
    H.x = h0; H.y = h1;
    L.x = __float2half_rn(v0 - __half2float(h0));
    L.y = __float2half_rn(v1 - __half2float(h1));
    *(__half2*)hi = H;
    *(__half2*)lo = L;
}

// ---------------- unified mma GEMM -------------------------------------------
// C[m][n] = sum_k A[m][k] * B[n][k]   (fp16 hi/lo split, fp32 accum)
// passes: Ah*Bh + Ah*Bl (+ Al*Bh when A is split)
// BM=128, BN=64, 256 thr, warp tile 32x32 (MA=2, NA=4), ldmatrix fragments.
template <int MODE, int K>
__global__ __launch_bounds__(256)
void mma_gemm(const float* __restrict__ bias, float* __restrict__ Cout,
              const float* __restrict__ amask, const unsigned char* __restrict__ pmask)
{
    constexpr int BM = 128, BN = 64, WM = 32, WN = 32;
    constexpr int MA = WM / 16, NA = WN / 8, NWX = BN / WN;
    constexpr int KC = K / 16;
    constexpr bool ALO = (MODE != 4);          // A has a lo component
    constexpr int LDA = 24;                    // padded halves per 16-k row
    constexpr int LDB = (MODE == 4) ? 72 : 24;
    constexpr int BSZ = (MODE == 4) ? 16 * 72 : BN * 24;

    __shared__ __align__(16) hf sAh[2][BM * LDA];
    __shared__ __align__(16) hf sAl[ALO ? 2 : 1][ALO ? BM * LDA : 8];
    __shared__ __align__(16) hf sBh[2][BSZ], sBl[2][BSZ];

    const int tid = threadIdx.x, wid = tid >> 5, lane = tid & 31;
    const int g = lane >> 2, tg = lane & 3;
    const int i4 = lane >> 3, r8 = lane & 7;   // ldmatrix: matrix idx, row
    const int m0 = blockIdx.y * BM, n0 = blockIdx.x * BN, zb = blockIdx.z;
    const int wm0 = (wid / NWX) * WM, wn0 = (wid % NWX) * WN;

    const hf *pAh, *pAl, *pBh, *pBl;
    size_t lda, ldb;
    if constexpr (MODE == 0)      { pAh = c_outs_hi; pAl = c_outs_lo; pBh = c_win_hi; pBl = c_win_lo; lda = ldb = 768; }
    else if constexpr (MODE == 1) { pAh = c_gs_hi;   pAl = c_gs_lo;
                                    pBh = c_win_hi + 768 * 768; pBl = c_win_lo + 768 * 768; lda = ldb = 768; }
    else if constexpr (MODE == 3) { pAh = g_qh + zb * 65536; pAl = g_ql + zb * 65536;
                                    pBh = g_kh + zb * 65536; pBl = g_kl + zb * 65536; lda = ldb = 64; }
    else if constexpr (MODE == 4) { pAh = g_e + (size_t)zb * 1048576; pAl = nullptr;
                                    pBh = g_vh + zb * 65536; pBl = g_vl + zb * 65536; lda = 1024; ldb = 64; }
    else                          { pAh = c_at_hi; pAl = c_at_lo; pBh = c_wout_hi; pBl = c_wout_lo; lda = ldb = 768; }

    uint4 ra_h, ra_l, rb_h, rb_l;
    uint2 r4_h, r4_l;

    auto ldA = [&](int k0) {
        const int r = tid >> 1, kc = (tid & 1) * 8;
        ra_h = *(const uint4*)(pAh + (size_t)(m0 + r) * lda + k0 + kc);
        if constexpr (ALO)
            ra_l = *(const uint4*)(pAl + (size_t)(m0 + r) * lda + k0 + kc);
    };
    auto stA = [&](int b_) {
        const int r = tid >> 1, kc = (tid & 1) * 8;
        *(uint4*)&sAh[b_][r * LDA + kc] = ra_h;
        if constexpr (ALO)
            *(uint4*)&sAl[b_][r * LDA + kc] = ra_l;
    };
    auto ldB = [&](int k0) {
        if constexpr (MODE == 4) {
            const int s = tid >> 4, d0 = (tid & 15) * 4;
            r4_h = *(const uint2*)(pBh + (size_t)(k0 + s) * 64 + d0);
            r4_l = *(const uint2*)(pBl + (size_t)(k0 + s) * 64 + d0);
        } else if (tid < 2 * BN) {
            const int r = tid >> 1, kc = (tid & 1) * 8;
            rb_h = *(const uint4*)(pBh + (size_t)(n0 + r) * ldb + k0 + kc);
            rb_l = *(const uint4*)(pBl + (size_t)(n0 + r) * ldb + k0 + kc);
        }
    };
    auto stB = [&](int b_) {
        if constexpr (MODE == 4) {          // keep v[s][d] layout; ldmatrix.trans later
            const int s = tid >> 4, d0 = (tid & 15) * 4;
            *(uint2*)&sBh[b_][s * LDB + d0] = r4_h;
            *(uint2*)&sBl[b_][s * LDB + d0] = r4_l;
        } else if (tid < 2 * BN) {
            const int r = tid >> 1, kc = (tid & 1) * 8;
            *(uint4*)&sBh[b_][r * LDB + kc] = rb_h;
            *(uint4*)&sBl[b_][r * LDB + kc] = rb_l;
        }
    };

    float acc[MA][NA][4];
#pragma unroll
    for (int i = 0; i < MA; i++)
#pragma unroll
        for (int j = 0; j < NA; j++)
#pragma unroll
            for (int u = 0; u < 4; u++) acc[i][j][u] = 0.f;

    auto comp = [&](int b_) {
        uint32_t afh[MA][4], afl[MA][4], bfh[NA][2], bfl[NA][2];
        // A fragments: matrix i: row += (i&1)*8, col = (i&2)?8:0
        const int arow = ((i4 & 1) << 3) + r8;
        const int acol = (i4 & 2) ? 8 : 0;
#pragma unroll
        for (int ma = 0; ma < MA; ma++) {
            const uint32_t ah = s2u(&sAh[b_][(wm0 + 16 * ma + arow) * LDA + acol]);
            ldsm4(afh[ma][0], afh[ma][1], afh[ma][2], afh[ma][3], ah);
            if constexpr (ALO) {
                const uint32_t al = s2u(&sAl[b_][(wm0 + 16 * ma + arow) * LDA + acol]);
                ldsm4(afl[ma][0], afl[ma][1], afl[ma][2], afl[ma][3], al);
            }
        }
        // B fragments
        if constexpr (MODE == 4) {
            // sB[s][d]; trans: matrix i: srow = (i&1)*8+r8, dcol = base + (i>>1)*8
            const int srow = ((i4 & 1) << 3) + r8;
            const int dadd = (i4 >> 1) << 3;
#pragma unroll
            for (int p = 0; p < NA / 2; p++) {
                const uint32_t bh = s2u(&sBh[b_][srow * LDB + wn0 + 16 * p + dadd]);
                ldsm4t(bfh[2 * p][0], bfh[2 * p][1], bfh[2 * p + 1][0], bfh[2 * p + 1][1], bh);
                const uint32_t bl = s2u(&sBl[b_][srow * LDB + wn0 + 16 * p + dadd]);
                ldsm4t(bfl[2 * p][0], bfl[2 * p][1], bfl[2 * p + 1][0], bfl[2 * p + 1][1], bl);
            }
        } else {
            // sB[n][k]; matrix i: nrow = (i>>1)*8+r8, col = (i&1)*8
            const int nrow = ((i4 >> 1) << 3) + r8;
            const int bcol = (i4 & 1) << 3;
#pragma unroll
            for (int p = 0; p < NA / 2; p++) {
                const uint32_t bh = s2u(&sBh[b_][(wn0 + 16 * p + nrow) * LDB + bcol]);
                ldsm4(bfh[2 * p][0], bfh[2 * p][1], bfh[2 * p + 1][0], bfh[2 * p + 1][1], bh);
                const uint32_t bl = s2u(&sBl[b_][(wn0 + 16 * p + nrow) * LDB + bcol]);
                ldsm4(bfl[2 * p][0], bfl[2 * p][1], bfl[2 * p + 1][0], bfl[2 * p + 1][1], bl);
            }
        }
#pragma unroll
        for (int na = 0; na < NA; na++)
#pragma unroll
            for (int ma = 0; ma < MA; ma++) {
                mma_f16(acc[ma][na], afh[ma], bfh[na][0], bfh[na][1]);
                mma_f16(acc[ma][na], afh[ma], bfl[na][0], bfl[na][1]);
                if constexpr (ALO) mma_f16(acc[ma][na], afl[ma], bfh[na][0], bfh[na][1]);
            }
    };

    ldA(0); ldB(0); stA(0); stB(0); __syncthreads();
    int b_ = 0;
    for (int c = 1; c < KC; c++) {
        ldA(c * 16); ldB(c * 16);
        comp(b_);
        stA(b_ ^ 1); stB(b_ ^ 1);
        __syncthreads();
        b_ ^= 1;
    }
    comp(b_);

    // ---------------- epilogue ----------------
#pragma unroll
    for (int ma = 0; ma < MA; ma++) {
#pragma unroll
        for (int hfi = 0; hfi < 2; hfi++) {
            const int gm = m0 + wm0 + 16 * ma + g + 8 * hfi;
            float rsum = 0.f;
            float rz = 1.f;
            if constexpr (MODE == 4) rz = 1.f / g_z[zb * 1024 + gm];
#pragma unroll
            for (int na = 0; na < NA; na++) {
                const int c0 = n0 + wn0 + 8 * na + 2 * tg;
                float v0 = acc[ma][na][hfi * 2], v1 = acc[ma][na][hfi * 2 + 1];
                if constexpr (MODE == 0) {
                    v0 = (v0 + bias[c0]) * 0.125f;
                    v1 = (v1 + bias[c0 + 1]) * 0.125f;
                    const int t = gm >> 3, b = gm & 7, h = c0 >> 6, d = c0 & 63;
                    const size_t off = ((size_t)(b * cH + h) * 1024 + t) * 64 + d;
                    split_store(g_qh + off, g_ql + off, v0, v1);
                } else if constexpr (MODE == 1) {
                    v0 += bias[c0]; v1 += bias[c0 + 1];
                    const int s = gm >> 3, b = gm & 7;
                    const bool isV = c0 >= 768;
                    const int cc = isV ? c0 - 768 : c0;
                    const int h = cc >> 6, d = cc & 63;
                    const size_t off = ((size_t)(b * cH + h) * 1024 + s) * 64 + d;
                    if (isV) split_store(g_vh + off, g_vl + off, v0, v1);
                    else     split_store(g_kh + off, g_kl + off, v0, v1);
                } else if constexpr (MODE == 3) {
                    const int b = zb / cH;
                    const float a0 = amask[(size_t)gm * 1024 + c0];
                    const float a1 = amask[(size_t)gm * 1024 + c0 + 1];
                    const float e0 = pmask[b * 1024 + c0]     ? 0.f : __expf(v0 + a0);
                    const float e1 = pmask[b * 1024 + c0 + 1] ? 0.f : __expf(v1 + a1);
                    rsum += e0 + e1;
                    __half2 E; E.x = __float2half_rn(e0); E.y = __float2half_rn(e1);
                    *(__half2*)&g_e[(size_t)zb * 1048576 + (size_t)gm * 1024 + c0] = E;
                } else if constexpr (MODE == 4) {
                    const int b = zb / cH, h = zb % cH;
                    const size_t off = ((size_t)gm * 8 + b) * 768 + h * 64 + c0;
                    split_store(c_at_hi + off, c_at_lo + off, v0 * rz, v1 * rz);
                } else {
                    float2 o;
                    o.x = v0 + bias[c0]; o.y = v1 + bias[c0 + 1];
                    *(float2*)&Cout[(size_t)gm * 768 + c0] = o;
                }
            }
            if constexpr (MODE == 3) {
                rsum += __shfl_xor_sync(0xffffffffu, rsum, 1);
                rsum += __shfl_xor_sync(0xffffffffu, rsum, 2);
                if (tg == 0) atomicAdd(&g_z[zb * 1024 + gm], rsum);
            }
        }
    }
}

// ---------------- fp32 -> fp16 hi/lo conversions -----------------------------
template <int W>
__global__ __launch_bounds__(256)
void conv_split(const float* __restrict__ src, int npairs)
{
    hf *hi, *lo;
    if constexpr (W == 0)      { hi = c_outs_hi; lo = c_outs_lo; }
    else if constexpr (W == 1) { hi = c_gs_hi;   lo = c_gs_lo; }
    else if constexpr (W == 2) { hi = c_win_hi;  lo = c_win_lo; }
    else                       { hi = c_wout_hi; lo = c_wout_lo; }
    const int i = blockIdx.x * 256 + threadIdx.x;
    if (i >= npairs) return;
    const float2 v = ((const float2*)src)[i];
    split_store(hi + 2 * i, lo + 2 * i, v.x, v.y);
}

// ---------------- BCE --------------------------------------------------------
__global__ __launch_bounds__(256)
void bce_kernel(float* __restrict__ out, const int* __restrict__ trel,
                const float* __restrict__ strat)
{
    const int t = blockIdx.x, b = blockIdx.y;
    __shared__ float srz[cH];
    if (threadIdx.x < cH)
        srz[threadIdx.x] = 1.f / g_z[(b * cH + threadIdx.x) * 1024 + t];
    __syncthreads();
    float ls = 0.f;
    for (int sp = threadIdx.x; sp < 512; sp += 256) {
        float aw0 = 0.f, aw1 = 0.f;
#pragma unroll
        for (int h = 0; h < cH; h++) {
            const __half2 e2 = *(const __half2*)
                &g_e[((size_t)(b * cH + h) * 1024 + t) * 1024 + 2 * sp];
            aw0 = fmaxf(aw0, __half2float(e2.x) * srz[h]);
            aw1 = fmaxf(aw1, __half2float(e2.y) * srz[h]);
        }
        const int2 rr = *(const int2*)&trel[((size_t)t * 8 + b) * 1024 + 2 * sp];
        if (rr.x) ls += (rr.x != 2) ? -fmaxf(logf(aw0), -100.f)
                                    : -fmaxf(log1pf(-aw0), -100.f);
        if (rr.y) ls += (rr.y != 2) ? -fmaxf(logf(aw1), -100.f)
                                    : -fmaxf(log1pf(-aw1), -100.f);
    }
#pragma unroll
    for (int o = 16; o; o >>= 1) ls += __shfl_xor_sync(0xffffffffu, ls, o);
    __shared__ float ws[8];
    if ((threadIdx.x & 31) == 0) ws[threadIdx.x >> 5] = ls;
    __syncthreads();
    if (threadIdx.x == 0) {
        float tot = 0.f;
#pragma unroll
        for (int w = 0; w < 8; w++) tot += ws[w];
        atomicAdd(&out[b], tot * strat[b]);
    }
}

// ---------------- helpers ----------------------------------------------------
__global__ void zero_loss(float* out) { if (threadIdx.x < cB) out[threadIdx.x] = 0.f; }
__global__ __launch_bounds__(256) void zero_z_kernel()
{
    const int i = blockIdx.x * 256 + threadIdx.x;
    if (i < ZS * 1024) g_z[i] = 0.f;
}
__global__ __launch_bounds__(256)
void copy_outs_kernel(float* __restrict__ dst, const float* __restrict__ src)
{
    const int i = blockIdx.x * 256 + threadIdx.x;
    ((float4*)dst)[i] = ((const float4*)src)[i];
}

// ---------------- entry point -------------------------------------------------
extern "C" void kernel_launch(void* const* d_in, const int* in_sizes, int n_in,
                              void* d_out, int out_size)
{
    const float*         outs   = (const float*)d_in[2];
    const float*         gstate = (const float*)d_in[3];
    const unsigned char* pmask  = (const unsigned char*)d_in[4];
    const float*         amask  = (const float*)d_in[5];
    const float*         strat  = (const float*)d_in[6];
    const int*           trel   = (const int*)d_in[7];
    const float*         b_in   = (const float*)d_in[9];
    const float*         b_out  = (const float*)d_in[11];
    float* out = (float*)d_out;

    float* out_loss = out;
    float* out_copy = out + cB;
    float* out_x    = out + cB + (size_t)1024 * cB * cE;

    // order chosen so ncu (-s 5 -c 1) captures mma_gemm<0> as launch #6
    conv_split<0><<<8192 * 768 / 2 / 256, 256>>>(outs,   8192 * 768 / 2);
    conv_split<1><<<8192 * 768 / 2 / 256, 256>>>(gstate, 8192 * 768 / 2);
    conv_split<2><<<2304 * 768 / 2 / 256, 256>>>((const float*)d_in[8],  2304 * 768 / 2);
    conv_split<3><<<768 * 768 / 2 / 256, 256>>>((const float*)d_in[10], 768 * 768 / 2);
    zero_z_kernel<<<ZS * 1024 / 256, 256>>>();

    // MODE 0: Q projection  (launch #6 — ncu capture target)
    mma_gemm<0, 768><<<dim3(12, 64, 1), 256>>>(b_in, nullptr, nullptr, nullptr);

    zero_loss<<<1, 32>>>(out_loss);
    copy_outs_kernel<<<(1024 * cB * cE / 4) / 256, 256>>>(out_copy, outs);

    // MODE 1: K+V fused
    mma_gemm<1, 768><<<dim3(24, 64, 1), 256>>>(b_in + 768, nullptr, nullptr, nullptr);
    // MODE 3: logits -> e + rowsums
    mma_gemm<3, 64><<<dim3(16, 8, 96), 256>>>(nullptr, nullptr, amask, pmask);
    // BCE
    bce_kernel<<<dim3(1024, cB), 256>>>(out_loss, trel, strat);
    // MODE 4: attn = e @ v / z
    mma_gemm<4, 1024><<<dim3(1, 8, 96), 256>>>(nullptr, nullptr, nullptr, nullptr);
    // MODE 5: out projection
    mma_gemm<5, 768><<<dim3(12, 64, 1), 256>>>(b_out, out_x, nullptr, nullptr);
}

// round 12
// speedup vs baseline: 2.0977x; 1.3162x over previous
#include <cuda_runtime.h>
#include <cuda_fp16.h>
#include <math.h>
#include <stdint.h>

constexpr int cB = 8, cE = 768, cH = 12;
constexpr int ZS = cB * cH;          // 96 (b,h) slices
using hf = __half;

// ---------------- device-global scratch --------------------------------------
// A-side operands (q, e, attn, outs, gs) are hi-only; B-side (weights, k, v) hi+lo.
#define DARR(n, sz) __device__ __align__(16) hf n[sz]
DARR(c_outs_hi, 8192 * 768);
DARR(c_gs_hi,   8192 * 768);
DARR(c_win_hi,  2304 * 768); DARR(c_win_lo,  2304 * 768);
DARR(c_wout_hi,  768 * 768); DARR(c_wout_lo,  768 * 768);
DARR(g_qh, ZS * 1024 * 64);                                // [z][t][d]
DARR(g_kh, ZS * 1024 * 64);  DARR(g_kl, ZS * 1024 * 64);   // [z][s][d]
DARR(g_vh, ZS * 1024 * 64);  DARR(g_vl, ZS * 1024 * 64);   // [z][s][d]
DARR(g_e,  (size_t)ZS * 1024 * 1024);                      // [z][t][s] fp16
DARR(c_at_hi, 8192 * 768);                                 // [(t*8+b)][e]
__device__ float g_z[ZS * 1024];

// ---------------- helpers ----------------------------------------------------
__device__ __forceinline__ void mma_f16(float* d, const uint32_t* a,
                                        uint32_t b0, uint32_t b1) {
    asm volatile(
        "mma.sync.aligned.m16n8k16.row.col.f32.f16.f16.f32 "
        "{%0,%1,%2,%3},{%4,%5,%6,%7},{%8,%9},{%0,%1,%2,%3};"
        : "+f"(d[0]), "+f"(d[1]), "+f"(d[2]), "+f"(d[3])
        : "r"(a[0]), "r"(a[1]), "r"(a[2]), "r"(a[3]), "r"(b0), "r"(b1));
}
__device__ __forceinline__ uint32_t s2u(const void* p) {
    return (uint32_t)__cvta_generic_to_shared(p);
}
__device__ __forceinline__ void ldsm4(uint32_t& a, uint32_t& b, uint32_t& c,
                                      uint32_t& d, uint32_t addr) {
    asm volatile("ldmatrix.sync.aligned.m8n8.x4.shared.b16 {%0,%1,%2,%3}, [%4];"
                 : "=r"(a), "=r"(b), "=r"(c), "=r"(d) : "r"(addr));
}
__device__ __forceinline__ void ldsm4t(uint32_t& a, uint32_t& b, uint32_t& c,
                                       uint32_t& d, uint32_t addr) {
    asm volatile("ldmatrix.sync.aligned.m8n8.x4.trans.shared.b16 {%0,%1,%2,%3}, [%4];"
                 : "=r"(a), "=r"(b), "=r"(c), "=r"(d) : "r"(addr));
}
__device__ __forceinline__ __half2 mk2(float a, float b) {
    __half2 h; h.x = __float2half_rn(a); h.y = __float2half_rn(b); return h;
}
__device__ __forceinline__ void split_store(hf* hi, hf* lo, float v0, float v1) {
    const __half2 H = mk2(v0, v1);
    *(__half2*)hi = H;
    *(__half2*)lo = mk2(v0 - __half2float(H.x), v1 - __half2float(H.y));
}

// ---------------- unified mma GEMM (2-pass asymmetric split) -----------------
// C[m][n] = sum_k A[m][k] * B[n][k] ≈ Ah*Bh + Ah*Bl; fp32 accum.
// BM=128; BN/WN template (128/64 wide, 64/32 for MODE4). 256 threads.
// MODE 0: q = outs@Wq^T (+b)*0.125 -> g_qh            (hi only)
// MODE 1: k,v = gs@Wkv^T (+b)      -> g_k*/g_v*       (hi+lo)
// MODE 3: e = exp(q@k^T + amask; pmask->0) -> g_e, rowsum -> g_z
// MODE 4: attn = (e@v^T)/z         -> c_at_hi         (hi only)
// MODE 5: x = attn@Wout^T (+b)     -> Cout fp32
template <int MODE, int K, int BN, int WN>
__global__ __launch_bounds__(256)
void mma_gemm(const float* __restrict__ bias, float* __restrict__ Cout,
              const float* __restrict__ amask, const unsigned char* __restrict__ pmask)
{
    constexpr int BM = 128, WM = 32;
    constexpr int MA = WM / 16, NA = WN / 8, NWX = BN / WN;
    constexpr int KC = K / 16;
    constexpr int LDA = 24;
    constexpr int LDB = (MODE == 4) ? 72 : 24;
    constexpr int BSZ = (MODE == 4) ? 16 * 72 : BN * 24;

    __shared__ __align__(16) hf sAh[2][BM * LDA];
    __shared__ __align__(16) hf sBh[2][BSZ], sBl[2][BSZ];

    const int tid = threadIdx.x, wid = tid >> 5, lane = tid & 31;
    const int g = lane >> 2, tg = lane & 3;
    const int i4 = lane >> 3, r8 = lane & 7;
    const int m0 = blockIdx.y * BM, n0 = blockIdx.x * BN, zb = blockIdx.z;
    const int wm0 = (wid / NWX) * WM, wn0 = (wid % NWX) * WN;

    const hf *pAh, *pBh, *pBl;
    size_t lda, ldb;
    if constexpr (MODE == 0)      { pAh = c_outs_hi; pBh = c_win_hi; pBl = c_win_lo; lda = ldb = 768; }
    else if constexpr (MODE == 1) { pAh = c_gs_hi;
                                    pBh = c_win_hi + 768 * 768; pBl = c_win_lo + 768 * 768; lda = ldb = 768; }
    else if constexpr (MODE == 3) { pAh = g_qh + zb * 65536;
                                    pBh = g_kh + zb * 65536; pBl = g_kl + zb * 65536; lda = ldb = 64; }
    else if constexpr (MODE == 4) { pAh = g_e + (size_t)zb * 1048576;
                                    pBh = g_vh + zb * 65536; pBl = g_vl + zb * 65536; lda = 1024; ldb = 64; }
    else                          { pAh = c_at_hi; pBh = c_wout_hi; pBl = c_wout_lo; lda = ldb = 768; }

    uint4 ra_h, rb_h, rb_l;
    uint2 r4_h, r4_l;

    auto ldA = [&](int k0) {
        const int r = tid >> 1, kc = (tid & 1) * 8;
        ra_h = *(const uint4*)(pAh + (size_t)(m0 + r) * lda + k0 + kc);
    };
    auto stA = [&](int b_) {
        const int r = tid >> 1, kc = (tid & 1) * 8;
        *(uint4*)&sAh[b_][r * LDA + kc] = ra_h;
    };
    auto ldB = [&](int k0) {
        if constexpr (MODE == 4) {
            const int s = tid >> 4, d0 = (tid & 15) * 4;
            r4_h = *(const uint2*)(pBh + (size_t)(k0 + s) * 64 + d0);
            r4_l = *(const uint2*)(pBl + (size_t)(k0 + s) * 64 + d0);
        } else {
            const int idx = tid & (2 * BN - 1);
            const int r = idx >> 1, kc = (idx & 1) * 8;
            if (2 * BN == 256 || tid < 2 * BN) {
                rb_h = *(const uint4*)(pBh + (size_t)(n0 + r) * ldb + k0 + kc);
                rb_l = *(const uint4*)(pBl + (size_t)(n0 + r) * ldb + k0 + kc);
            }
        }
    };
    auto stB = [&](int b_) {
        if constexpr (MODE == 4) {
            const int s = tid >> 4, d0 = (tid & 15) * 4;
            *(uint2*)&sBh[b_][s * LDB + d0] = r4_h;
            *(uint2*)&sBl[b_][s * LDB + d0] = r4_l;
        } else {
            const int idx = tid & (2 * BN - 1);
            const int r = idx >> 1, kc = (idx & 1) * 8;
            if (2 * BN == 256 || tid < 2 * BN) {
                *(uint4*)&sBh[b_][r * LDB + kc] = rb_h;
                *(uint4*)&sBl[b_][r * LDB + kc] = rb_l;
            }
        }
    };

    float acc[MA][NA][4];
#pragma unroll
    for (int i = 0; i < MA; i++)
#pragma unroll
        for (int j = 0; j < NA; j++)
#pragma unroll
            for (int u = 0; u < 4; u++) acc[i][j][u] = 0.f;

    auto comp = [&](int b_) {
        uint32_t afh[MA][4], bfh[NA][2], bfl[NA][2];
        const int arow = ((i4 & 1) << 3) + r8;
        const int acol = (i4 & 2) ? 8 : 0;
#pragma unroll
        for (int ma = 0; ma < MA; ma++) {
            const uint32_t ah = s2u(&sAh[b_][(wm0 + 16 * ma + arow) * LDA + acol]);
            ldsm4(afh[ma][0], afh[ma][1], afh[ma][2], afh[ma][3], ah);
        }
        if constexpr (MODE == 4) {
            const int srow = ((i4 & 1) << 3) + r8;
            const int dadd = (i4 >> 1) << 3;
#pragma unroll
            for (int p = 0; p < NA / 2; p++) {
                const uint32_t bh = s2u(&sBh[b_][srow * LDB + wn0 + 16 * p + dadd]);
                ldsm4t(bfh[2 * p][0], bfh[2 * p][1], bfh[2 * p + 1][0], bfh[2 * p + 1][1], bh);
                const uint32_t bl = s2u(&sBl[b_][srow * LDB + wn0 + 16 * p + dadd]);
                ldsm4t(bfl[2 * p][0], bfl[2 * p][1], bfl[2 * p + 1][0], bfl[2 * p + 1][1], bl);
            }
        } else {
            const int nrow = ((i4 >> 1) << 3) + r8;
            const int bcol = (i4 & 1) << 3;
#pragma unroll
            for (int p = 0; p < NA / 2; p++) {
                const uint32_t bh = s2u(&sBh[b_][(wn0 + 16 * p + nrow) * LDB + bcol]);
                ldsm4(bfh[2 * p][0], bfh[2 * p][1], bfh[2 * p + 1][0], bfh[2 * p + 1][1], bh);
                const uint32_t bl = s2u(&sBl[b_][(wn0 + 16 * p + nrow) * LDB + bcol]);
                ldsm4(bfl[2 * p][0], bfl[2 * p][1], bfl[2 * p + 1][0], bfl[2 * p + 1][1], bl);
            }
        }
#pragma unroll
        for (int na = 0; na < NA; na++)
#pragma unroll
            for (int ma = 0; ma < MA; ma++) {
                mma_f16(acc[ma][na], afh[ma], bfh[na][0], bfh[na][1]);
                mma_f16(acc[ma][na], afh[ma], bfl[na][0], bfl[na][1]);
            }
    };

    ldA(0); ldB(0); stA(0); stB(0); __syncthreads();
    int b_ = 0;
    for (int c = 1; c < KC; c++) {
        ldA(c * 16); ldB(c * 16);
        comp(b_);
        stA(b_ ^ 1); stB(b_ ^ 1);
        __syncthreads();
        b_ ^= 1;
    }
    comp(b_);

    // ---------------- epilogue ----------------
#pragma unroll
    for (int ma = 0; ma < MA; ma++) {
#pragma unroll
        for (int hfi = 0; hfi < 2; hfi++) {
            const int gm = m0 + wm0 + 16 * ma + g + 8 * hfi;
            float rsum = 0.f;
            float rz = 1.f;
            if constexpr (MODE == 4) rz = 1.f / g_z[zb * 1024 + gm];
#pragma unroll
            for (int na = 0; na < NA; na++) {
                const int c0 = n0 + wn0 + 8 * na + 2 * tg;
                float v0 = acc[ma][na][hfi * 2], v1 = acc[ma][na][hfi * 2 + 1];
                if constexpr (MODE == 0) {
                    v0 = (v0 + bias[c0]) * 0.125f;
                    v1 = (v1 + bias[c0 + 1]) * 0.125f;
                    const int t = gm >> 3, b = gm & 7, h = c0 >> 6, d = c0 & 63;
                    const size_t off = ((size_t)(b * cH + h) * 1024 + t) * 64 + d;
                    *(__half2*)&g_qh[off] = mk2(v0, v1);
                } else if constexpr (MODE == 1) {
                    v0 += bias[c0]; v1 += bias[c0 + 1];
                    const int s = gm >> 3, b = gm & 7;
                    const bool isV = c0 >= 768;
                    const int cc = isV ? c0 - 768 : c0;
                    const int h = cc >> 6, d = cc & 63;
                    const size_t off = ((size_t)(b * cH + h) * 1024 + s) * 64 + d;
                    if (isV) split_store(g_vh + off, g_vl + off, v0, v1);
                    else     split_store(g_kh + off, g_kl + off, v0, v1);
                } else if constexpr (MODE == 3) {
                    const int b = zb / cH;
                    const float a0 = amask[(size_t)gm * 1024 + c0];
                    const float a1 = amask[(size_t)gm * 1024 + c0 + 1];
                    const float e0 = pmask[b * 1024 + c0]     ? 0.f : __expf(v0 + a0);
                    const float e1 = pmask[b * 1024 + c0 + 1] ? 0.f : __expf(v1 + a1);
                    rsum += e0 + e1;
                    *(__half2*)&g_e[(size_t)zb * 1048576 + (size_t)gm * 1024 + c0] = mk2(e0, e1);
                } else if constexpr (MODE == 4) {
                    const int b = zb / cH, h = zb % cH;
                    const size_t off = ((size_t)gm * 8 + b) * 768 + h * 64 + c0;
                    *(__half2*)&c_at_hi[off] = mk2(v0 * rz, v1 * rz);
                } else {
                    float2 o;
                    o.x = v0 + bias[c0]; o.y = v1 + bias[c0 + 1];
                    *(float2*)&Cout[(size_t)gm * 768 + c0] = o;
                }
            }
            if constexpr (MODE == 3) {
                rsum += __shfl_xor_sync(0xffffffffu, rsum, 1);
                rsum += __shfl_xor_sync(0xffffffffu, rsum, 2);
                if (tg == 0) atomicAdd(&g_z[zb * 1024 + gm], rsum);
            }
        }
    }
}

// ---------------- fp32 -> fp16 conversions (hi, optional lo) -----------------
template <int W, bool LO>
__global__ __launch_bounds__(256)
void conv_split(const float* __restrict__ src, int npairs)
{
    hf *hi, *lo = nullptr;
    if constexpr (W == 0)      { hi = c_outs_hi; }
    else if constexpr (W == 1) { hi = c_gs_hi; }
    else if constexpr (W == 2) { hi = c_win_hi;  lo = c_win_lo; }
    else                       { hi = c_wout_hi; lo = c_wout_lo; }
    const int i = blockIdx.x * 256 + threadIdx.x;
    if (i >= npairs) return;
    const float2 v = ((const float2*)src)[i];
    const __half2 H = mk2(v.x, v.y);
    ((__half2*)hi)[i] = H;
    if constexpr (LO)
        ((__half2*)lo)[i] = mk2(v.x - __half2float(H.x), v.y - __half2float(H.y));
}

// ---------------- BCE --------------------------------------------------------
__global__ __launch_bounds__(256)
void bce_kernel(float* __restrict__ out, const int* __restrict__ trel,
                const float* __restrict__ strat)
{
    const int t = blockIdx.x, b = blockIdx.y;
    __shared__ float srz[cH];
    if (threadIdx.x < cH)
        srz[threadIdx.x] = 1.f / g_z[(b * cH + threadIdx.x) * 1024 + t];
    __syncthreads();
    float ls = 0.f;
    for (int sp = threadIdx.x; sp < 512; sp += 256) {
        float aw0 = 0.f, aw1 = 0.f;
#pragma unroll
        for (int h = 0; h < cH; h++) {
            const __half2 e2 = *(const __half2*)
                &g_e[((size_t)(b * cH + h) * 1024 + t) * 1024 + 2 * sp];
            aw0 = fmaxf(aw0, __half2float(e2.x) * srz[h]);
            aw1 = fmaxf(aw1, __half2float(e2.y) * srz[h]);
        }
        const int2 rr = *(const int2*)&trel[((size_t)t * 8 + b) * 1024 + 2 * sp];
        if (rr.x) ls += (rr.x != 2) ? -fmaxf(logf(aw0), -100.f)
                                    : -fmaxf(log1pf(-aw0), -100.f);
        if (rr.y) ls += (rr.y != 2) ? -fmaxf(logf(aw1), -100.f)
                                    : -fmaxf(log1pf(-aw1), -100.f);
    }
#pragma unroll
    for (int o = 16; o; o >>= 1) ls += __shfl_xor_sync(0xffffffffu, ls, o);
    __shared__ float ws[8];
    if ((threadIdx.x & 31) == 0) ws[threadIdx.x >> 5] = ls;
    __syncthreads();
    if (threadIdx.x == 0) {
        float tot = 0.f;
#pragma unroll
        for (int w = 0; w < 8; w++) tot += ws[w];
        atomicAdd(&out[b], tot * strat[b]);
    }
}

// ---------------- helpers ----------------------------------------------------
__global__ void zero_loss(float* out) { if (threadIdx.x < cB) out[threadIdx.x] = 0.f; }
__global__ __launch_bounds__(256) void zero_z_kernel()
{
    const int i = blockIdx.x * 256 + threadIdx.x;
    if (i < ZS * 1024) g_z[i] = 0.f;
}
__global__ __launch_bounds__(256)
void copy_outs_kernel(float* __restrict__ dst, const float* __restrict__ src)
{
    const int i = blockIdx.x * 256 + threadIdx.x;
    ((float4*)dst)[i] = ((const float4*)src)[i];
}

// ---------------- entry point -------------------------------------------------
extern "C" void kernel_launch(void* const* d_in, const int* in_sizes, int n_in,
                              void* d_out, int out_size)
{
    const float*         outs   = (const float*)d_in[2];
    const float*         gstate = (const float*)d_in[3];
    const unsigned char* pmask  = (const unsigned char*)d_in[4];
    const float*         amask  = (const float*)d_in[5];
    const float*         strat  = (const float*)d_in[6];
    const int*           trel   = (const int*)d_in[7];
    const float*         b_in   = (const float*)d_in[9];
    const float*         b_out  = (const float*)d_in[11];
    float* out = (float*)d_out;

    float* out_loss = out;
    float* out_copy = out + cB;
    float* out_x    = out + cB + (size_t)1024 * cB * cE;

    conv_split<0, false><<<8192 * 768 / 2 / 256, 256>>>(outs,   8192 * 768 / 2);
    conv_split<1, false><<<8192 * 768 / 2 / 256, 256>>>(gstate, 8192 * 768 / 2);
    conv_split<2, true ><<<2304 * 768 / 2 / 256, 256>>>((const float*)d_in[8],  2304 * 768 / 2);
    conv_split<3, true ><<<768 * 768 / 2 / 256, 256>>>((const float*)d_in[10], 768 * 768 / 2);
    zero_z_kernel<<<ZS * 1024 / 256, 256>>>();

    // MODE 0: Q projection (launch #6 — ncu capture target)
    mma_gemm<0, 768, 128, 64><<<dim3(6, 64, 1), 256>>>(b_in, nullptr, nullptr, nullptr);

    zero_loss<<<1, 32>>>(out_loss);
    copy_outs_kernel<<<(1024 * cB * cE / 4) / 256, 256>>>(out_copy, outs);

    // MODE 1: K+V fused projection
    mma_gemm<1, 768, 128, 64><<<dim3(12, 64, 1), 256>>>(b_in + 768, nullptr, nullptr, nullptr);
    // MODE 3: logits -> e + rowsums
    mma_gemm<3, 64, 128, 64><<<dim3(8, 8, 96), 256>>>(nullptr, nullptr, amask, pmask);
    // BCE
    bce_kernel<<<dim3(1024, cB), 256>>>(out_loss, trel, strat);
    // MODE 4: attn = e @ v / z
    mma_gemm<4, 1024, 64, 32><<<dim3(1, 8, 96), 256>>>(nullptr, nullptr, nullptr, nullptr);
    // MODE 5: out projection
    mma_gemm<5, 768, 128, 64><<<dim3(6, 64, 1), 256>>>(b_out, out_x, nullptr, nullptr);
}